// round 2
// baseline (speedup 1.0000x reference)
#include <cuda_runtime.h>
#include <cstdint>

// Problem constants
#define Bn      8
#define Cn      128
#define HWn     262144          // 512*512
#define SCALESn 4
#define NSEGn   1024
#define EMBEDn  192
#define TOKROWS 1025
#define TOK_SIZE   (Bn*TOKROWS*EMBEDn)       // 1,574,400 per scale
#define SEG_TOTAL  (Bn*SCALESn*HWn)          // 8,388,608
#define SEG_OUT_OFF ((size_t)SCALESn*TOK_SIZE) // 6,297,600

// ---------------- scratch (static device globals; no runtime alloc) ----------
__device__ float g_xt[(size_t)Bn*HWn*Cn];      // 1 GB: x transposed to [b][pixel][c]
__device__ int   g_sorted[SEG_TOTAL];          // sorted pixel ids per (b,scale)
__device__ int   g_cnt[Bn*SCALESn*NSEGn];      // per-segment counts
__device__ int   g_off[Bn*SCALESn*NSEGn];      // exclusive offsets
__device__ int   g_cursor[Bn*SCALESn*NSEGn];   // scatter cursors
__device__ float g_sums[(size_t)SCALESn*Bn*NSEGn*Cn]; // [s][b][n][c]

// ---------------- K0: zero counts ----------------
__global__ void k_zero()
{
    int i = blockIdx.x * 1024 + threadIdx.x;
    if (i < Bn*SCALESn*NSEGn) g_cnt[i] = 0;
}

// ---------------- K1: transpose x [b][c][p] -> g_xt [b][p][c] ----------------
// tile: 64 pixels x 128 channels per block
__global__ void k_transpose(const float* __restrict__ x)
{
    __shared__ float sm[64 * 129];
    int b  = blockIdx.y;
    int p0 = blockIdx.x * 64;
    const float* xb = x + (size_t)b * Cn * HWn;
    int t = threadIdx.x;

#pragma unroll
    for (int it = 0; it < 32; ++it) {
        int i  = it * 256 + t;
        int c  = i >> 6;
        int px = i & 63;
        sm[px * 129 + c] = xb[(size_t)c * HWn + p0 + px];
    }
    __syncthreads();
#pragma unroll
    for (int it = 0; it < 8; ++it) {
        int i  = it * 256 + t;
        int px = i >> 5;
        int c4 = i & 31;
        float4 v;
        v.x = sm[px * 129 + c4 * 4 + 0];
        v.y = sm[px * 129 + c4 * 4 + 1];
        v.z = sm[px * 129 + c4 * 4 + 2];
        v.w = sm[px * 129 + c4 * 4 + 3];
        *reinterpret_cast<float4*>(&g_xt[((size_t)b * HWn + p0 + px) * Cn + c4 * 4]) = v;
    }
}

// ---------------- K2: histogram (privatized in shared) ----------------
// 256 blocks: bs = blockIdx.x/8 in [0,32), chunk = blockIdx.x%8 (32768 px each)
__global__ void k_hist(const int* __restrict__ seg)
{
    __shared__ int h[NSEGn];
    int bs = blockIdx.x >> 3;
    int chunk = blockIdx.x & 7;
    int t = threadIdx.x;
    for (int i = t; i < NSEGn; i += 256) h[i] = 0;
    __syncthreads();
    const int4* s4 = reinterpret_cast<const int4*>(seg + (size_t)bs * HWn + (size_t)chunk * 32768);
#pragma unroll 4
    for (int it = 0; it < 32; ++it) {
        int4 v = s4[it * 256 + t];
        atomicAdd(&h[v.x], 1);
        atomicAdd(&h[v.y], 1);
        atomicAdd(&h[v.z], 1);
        atomicAdd(&h[v.w], 1);
    }
    __syncthreads();
    for (int i = t; i < NSEGn; i += 256) atomicAdd(&g_cnt[bs * NSEGn + i], h[i]);
}

// ---------------- K3: exclusive scan of 1024 counts per (b,scale) ----------------
__global__ void k_scan()
{
    int bs = blockIdx.x;
    int t = threadIdx.x;
    int lane = t & 31, wid = t >> 5;
    int v = g_cnt[bs * NSEGn + t];
    int x = v;
#pragma unroll
    for (int d = 1; d < 32; d <<= 1) {
        int y = __shfl_up_sync(0xffffffffu, x, d);
        if (lane >= d) x += y;
    }
    __shared__ int ws[32];
    if (lane == 31) ws[wid] = x;
    __syncthreads();
    if (wid == 0) {
        int s = ws[lane];
#pragma unroll
        for (int d = 1; d < 32; d <<= 1) {
            int y = __shfl_up_sync(0xffffffffu, s, d);
            if (lane >= d) s += y;
        }
        ws[lane] = s;
    }
    __syncthreads();
    int excl = x - v + (wid ? ws[wid - 1] : 0);
    g_off[bs * NSEGn + t]    = excl;
    g_cursor[bs * NSEGn + t] = excl;
}

// ---------------- K4: scatter pixel indices into per-segment lists ----------------
__global__ void k_scatter(const int* __restrict__ seg)
{
    int bs = blockIdx.x >> 3;
    int chunk = blockIdx.x & 7;
    int t = threadIdx.x;
    const int4* s4 = reinterpret_cast<const int4*>(seg + (size_t)bs * HWn + (size_t)chunk * 32768);
    int* cur = &g_cursor[bs * NSEGn];
    int* dst = &g_sorted[(size_t)bs * HWn];
#pragma unroll 2
    for (int it = 0; it < 32; ++it) {
        int i4 = it * 256 + t;
        int4 v = s4[i4];
        int px = chunk * 32768 + i4 * 4;
        int p;
        p = atomicAdd(cur + v.x, 1); dst[p] = px + 0;
        p = atomicAdd(cur + v.y, 1); dst[p] = px + 1;
        p = atomicAdd(cur + v.z, 1); dst[p] = px + 2;
        p = atomicAdd(cur + v.w, 1); dst[p] = px + 3;
    }
}

// ---------------- K5: segment-sum via sorted gather (no atomics) ----------------
// grid 2048: b = bx>>8, s = (bx>>6)&3, g = bx&63. Warp w handles segs g*16+w*2+{0,1}.
// Lane owns 4 channels (c = 4*lane .. 4*lane+3); per pixel one coalesced 512B row.
__global__ void k_reduce()
{
    int bx = blockIdx.x;
    int b = bx >> 8;
    int s = (bx >> 6) & 3;
    int g = bx & 63;
    int bs = b * SCALESn + s;
    int w = threadIdx.x >> 5, lane = threadIdx.x & 31;
    const float* xb = g_xt + (size_t)b * HWn * Cn;

    for (int k = 0; k < 2; ++k) {
        int sg  = g * 16 + w * 2 + k;
        int off = g_off[bs * NSEGn + sg];
        int cnt = g_cnt[bs * NSEGn + sg];
        const int* list = g_sorted + (size_t)bs * HWn + off;

        float ax = 0.f, ay = 0.f, az = 0.f, aw = 0.f;
        int i0 = 0;
        for (; i0 + 32 <= cnt; i0 += 32) {
            int pl = list[i0 + lane];
#pragma unroll 8
            for (int j = 0; j < 32; ++j) {
                int p = __shfl_sync(0xffffffffu, pl, j);
                float4 v = *reinterpret_cast<const float4*>(xb + (size_t)p * Cn + lane * 4);
                ax += v.x; ay += v.y; az += v.z; aw += v.w;
            }
        }
        if (i0 < cnt) {
            int idx = i0 + lane;
            int pl = (idx < cnt) ? list[idx] : 0;
            int m = cnt - i0;
            for (int j = 0; j < m; ++j) {
                int p = __shfl_sync(0xffffffffu, pl, j);
                float4 v = *reinterpret_cast<const float4*>(xb + (size_t)p * Cn + lane * 4);
                ax += v.x; ay += v.y; az += v.z; aw += v.w;
            }
        }
        float4 acc = make_float4(ax, ay, az, aw);
        *reinterpret_cast<float4*>(
            &g_sums[((size_t)(s * Bn + b) * NSEGn + sg) * Cn + lane * 4]) = acc;
    }
}

// ---------------- K6: 1x1 conv over channels: tok = (sums/cnt) @ W^T + bias ------
// block: 32 rows x 192 outputs; thread (ty,tx): rows ty*4+{0..3}, outs tx*6+{0..5}
__global__ void k_conv(const float* __restrict__ wgt,
                       const float* __restrict__ bias,
                       float* __restrict__ out)
{
    __shared__ float shm[32 * 128];
    __shared__ float shw[32 * 193];
    int t = threadIdx.x;
    int r0 = blockIdx.x * 32;

#pragma unroll
    for (int it = 0; it < 4; ++it) {
        int i = it * 256 + t;      // float4 index (1024 total)
        int row = i >> 5;
        int c4 = i & 31;
        *reinterpret_cast<float4*>(&shm[row * 128 + c4 * 4]) =
            *reinterpret_cast<const float4*>(&g_sums[(size_t)(r0 + row) * Cn + c4 * 4]);
    }

    int ty = t >> 5, tx = t & 31;
    float acc[4][6];
#pragma unroll
    for (int i = 0; i < 4; ++i)
#pragma unroll
        for (int j = 0; j < 6; ++j) acc[i][j] = 0.f;

    for (int cb = 0; cb < 4; ++cb) {
        __syncthreads();
#pragma unroll
        for (int it = 0; it < 24; ++it) {
            int i = it * 256 + t;  // 6144 elements
            int e = i >> 5;
            int c = i & 31;
            shw[c * 193 + e] = wgt[e * 128 + cb * 32 + c];
        }
        __syncthreads();
#pragma unroll
        for (int c = 0; c < 32; ++c) {
            float wv[6], mv[4];
#pragma unroll
            for (int j = 0; j < 6; ++j) wv[j] = shw[c * 193 + tx * 6 + j];
#pragma unroll
            for (int i = 0; i < 4; ++i) mv[i] = shm[(ty * 4 + i) * 128 + cb * 32 + c];
#pragma unroll
            for (int i = 0; i < 4; ++i)
#pragma unroll
                for (int j = 0; j < 6; ++j) acc[i][j] += mv[i] * wv[j];
        }
    }

    float bv[6];
#pragma unroll
    for (int j = 0; j < 6; ++j) bv[j] = __ldg(&bias[tx * 6 + j]);

#pragma unroll
    for (int i = 0; i < 4; ++i) {
        int r = r0 + ty * 4 + i;       // r = ((s*B + b)*1024 + n)
        int s  = r >> 13;
        int bb = (r >> 10) & 7;
        int n  = r & 1023;
        int cnt = g_cnt[(bb * SCALESn + s) * NSEGn + n];
        float inv = 1.0f / fmaxf((float)cnt, 1.0f);
        float* o = out + (size_t)s * TOK_SIZE
                       + (size_t)bb * TOKROWS * EMBEDn
                       + (size_t)(n + 1) * EMBEDn + tx * 6;
#pragma unroll
        for (int j = 0; j < 6; ++j) o[j] = acc[i][j] * inv + bv[j];
    }
}

// ---------------- K7: cls-token row (n = 0), identical for all (s,b) ----------
__global__ void k_cls(const float* __restrict__ wgt,
                      const float* __restrict__ bias,
                      const float* __restrict__ ct,
                      const float* __restrict__ cp,
                      float* __restrict__ out)
{
    int e = threadIdx.x;
    if (e >= EMBEDn) return;
    float a = bias[e];
    for (int c = 0; c < Cn; ++c)
        a += wgt[e * 128 + c] * (ct[c] + cp[c]);
    for (int s = 0; s < SCALESn; ++s)
        for (int b = 0; b < Bn; ++b)
            out[(size_t)s * TOK_SIZE + (size_t)b * TOKROWS * EMBEDn + e] = a;
}

// ---------------- K8: segments passthrough (int -> float cast) ----------------
__global__ void k_segout(const int* __restrict__ seg, float* __restrict__ out)
{
    int i = blockIdx.x * blockDim.x + threadIdx.x;   // int4 index
    const int4* s4 = reinterpret_cast<const int4*>(seg);
    int4 v = s4[i];
    float4 o = make_float4((float)v.x, (float)v.y, (float)v.z, (float)v.w);
    reinterpret_cast<float4*>(out + SEG_OUT_OFF)[i] = o;
}

// ---------------- launch ----------------
extern "C" void kernel_launch(void* const* d_in, const int* in_sizes, int n_in,
                              void* d_out, int out_size)
{
    const float* x   = (const float*)d_in[0];
    const int*   seg = (const int*)d_in[1];
    const float* ct  = (const float*)d_in[2];
    const float* cp  = (const float*)d_in[3];
    const float* cw  = (const float*)d_in[4];
    const float* cb  = (const float*)d_in[5];
    float* out = (float*)d_out;

    k_zero<<<32, 1024>>>();
    k_transpose<<<dim3(HWn / 64, Bn), 256>>>(x);
    k_hist<<<256, 256>>>(seg);
    k_scan<<<Bn * SCALESn, 1024>>>();
    k_scatter<<<256, 256>>>(seg);
    k_reduce<<<2048, 256>>>();
    k_conv<<<(SCALESn * Bn * NSEGn) / 32, 256>>>(cw, cb, out);
    k_cls<<<1, 192>>>(cw, cb, ct, cp, out);
    k_segout<<<SEG_TOTAL / 4 / 256, 256>>>(seg, out);
}